// round 13
// baseline (speedup 1.0000x reference)
#include <cuda_runtime.h>

#define CIN   256
#define HH    56
#define WW    56
#define NPIX  3136
#define BATCH 8

// Scratch (static device globals — allocation-free)
__device__ float g_q[BATCH * 32 * NPIX];
__device__ float g_k[BATCH * 32 * NPIX];
__device__ float g_v[BATCH * 256 * NPIX];

// ---------------------------------------------------------------------------
// 3x3 SAME conv, NCHW / OIHW. Block: 32 out-channels x (4 rows x 56 cols).
// Thread micro-tile: 4 co x 7 px. Cin chunked by 16 through shared memory.
// ---------------------------------------------------------------------------
__global__ __launch_bounds__(256) void conv3x3_kernel(
    const float* __restrict__ x, const float* __restrict__ w,
    const float* __restrict__ bias, float* __restrict__ y, int Cout)
{
    __shared__ float sx[16 * 6 * 58];   // [ci][row(6)][col(58)], halo + zero pad
    __shared__ float sw[144 * 33];      // [(ci*9+tap)][co], stride 33 (conflict-free)

    const int tid  = threadIdx.x;
    const int h0   = blockIdx.x * 4;
    const int co0  = blockIdx.y * 32;
    const int b    = blockIdx.z;

    const int cog  = tid & 7;          // 8 co-groups
    const int pxg  = tid >> 3;         // 32 px-groups
    const int prow = pxg >> 3;         // 0..3
    const int pcol = (pxg & 7) * 7;    // 0,7,...,49
    const int cob  = cog * 4;          // co base within tile

    float acc[4][7];
#pragma unroll
    for (int m = 0; m < 4; m++)
#pragma unroll
        for (int j = 0; j < 7; j++) acc[m][j] = 0.f;

    const float* xb = x + (size_t)b * CIN * NPIX;

    for (int ci0 = 0; ci0 < CIN; ci0 += 16) {
        __syncthreads();
        // Load x chunk with halo (rows h0-1..h0+4, cols -1..56), zero-padded.
        for (int idx = tid; idx < 16 * 6 * 58; idx += 256) {
            int ci  = idx / 348;
            int rem = idx - ci * 348;
            int r   = rem / 58;
            int cc  = rem - r * 58;
            int row = h0 - 1 + r;
            int col = cc - 1;
            float v = 0.f;
            if ((unsigned)row < 56u && (unsigned)col < 56u)
                v = xb[(ci0 + ci) * NPIX + row * WW + col];
            sx[idx] = v;
        }
        // Load weights: global-coalesced in (ci*9+tap); smem stride 33.
        const float* wbase = w + (size_t)co0 * (CIN * 9) + ci0 * 9;
        for (int idx = tid; idx < 32 * 144; idx += 256) {
            int co = idx / 144;
            int ct = idx - co * 144;
            sw[ct * 33 + co] = wbase[(size_t)co * (CIN * 9) + ct];
        }
        __syncthreads();

#pragma unroll 1
        for (int ci = 0; ci < 16; ci++) {
#pragma unroll 1
            for (int kh = 0; kh < 3; kh++) {
                float xv[9];
                const float* sxp = sx + ci * 348 + (prow + kh) * 58 + pcol;
#pragma unroll
                for (int j = 0; j < 9; j++) xv[j] = sxp[j];
                const float* swp = sw + (ci * 9 + kh * 3) * 33 + cob;
#pragma unroll
                for (int kw = 0; kw < 3; kw++) {
                    float w0 = swp[kw * 33 + 0];
                    float w1 = swp[kw * 33 + 1];
                    float w2 = swp[kw * 33 + 2];
                    float w3 = swp[kw * 33 + 3];
#pragma unroll
                    for (int j = 0; j < 7; j++) {
                        float xvj = xv[j + kw];
                        acc[0][j] += w0 * xvj;
                        acc[1][j] += w1 * xvj;
                        acc[2][j] += w2 * xvj;
                        acc[3][j] += w3 * xvj;
                    }
                }
            }
        }
    }

#pragma unroll
    for (int m = 0; m < 4; m++) {
        float bv = bias[co0 + cob + m];
        float* yp = y + ((size_t)(b * Cout + co0 + cob + m)) * NPIX
                      + (h0 + prow) * WW + pcol;
#pragma unroll
        for (int j = 0; j < 7; j++) yp[j] = acc[m][j] + bv;
    }
}

// ---------------------------------------------------------------------------
// Fused flash-attention: per (b, 64-query tile); loops 49 key tiles of 64.
// O accum: 8i x 8c per thread, c interleaved (cg + 32n) for conflict-free V.
// ---------------------------------------------------------------------------
#define OFF_QS   0
#define OFF_KS   2048
#define OFF_SS   4096
#define SS_LD    65
#define OFF_SM   8256
#define OFF_SL   8320
#define OFF_SAL  8384
#define OFF_RED  8448
#define OFF_VS   8704
#define VS_LD    257
#define SMEM_FLOATS 25152   /* 100608 bytes */

__global__ __launch_bounds__(256, 2) void attn_kernel(
    const float* __restrict__ x, const float* __restrict__ gamma_p,
    float* __restrict__ out)
{
    extern __shared__ float sh[];
    const int tid = threadIdx.x;
    const int i0  = blockIdx.x * 64;
    const int b   = blockIdx.y;
    const int ig  = tid >> 5;   // 0..7 : query sub-block
    const int cg  = tid & 31;   // channel lane

    const float* qb = g_q + (size_t)b * 32 * NPIX;
    const float* kb = g_k + (size_t)b * 32 * NPIX;
    const float* vb = g_v + (size_t)b * 256 * NPIX;

    // Q tile: Qs[d][ii]
    for (int idx = tid; idx < 2048; idx += 256) {
        int d = idx >> 6, ii = idx & 63;
        sh[OFF_QS + idx] = qb[d * NPIX + i0 + ii];
    }
    if (tid < 64) {
        sh[OFF_SM + tid] = -1e30f;
        sh[OFF_SL + tid] = 0.f;
    }

    float acc[8][8];
#pragma unroll
    for (int m = 0; m < 8; m++)
#pragma unroll
        for (int n = 0; n < 8; n++) acc[m][n] = 0.f;

    for (int jt = 0; jt < 49; jt++) {
        const int j0 = jt * 64;
        __syncthreads();   // prior PV reads of Ks/Vs/Ss complete
        for (int idx = tid; idx < 2048; idx += 256) {
            int d = idx >> 6, jj = idx & 63;
            sh[OFF_KS + idx] = kb[d * NPIX + j0 + jj];
        }
        for (int idx = tid; idx < 16384; idx += 256) {
            int c = idx >> 6, jj = idx & 63;
            sh[OFF_VS + jj * VS_LD + c] = vb[c * NPIX + j0 + jj];
        }
        __syncthreads();

        // S[ii][jj] = sum_d Q[d][ii] K[d][jj]  (4x4 micro per thread)
        {
            const int jt4 = (tid & 15) * 4;
            const int it4 = (tid >> 4) * 4;
            float s00=0,s01=0,s02=0,s03=0, s10=0,s11=0,s12=0,s13=0;
            float s20=0,s21=0,s22=0,s23=0, s30=0,s31=0,s32=0,s33=0;
#pragma unroll 8
            for (int d = 0; d < 32; d++) {
                float4 q4 = *(const float4*)&sh[OFF_QS + d * 64 + it4];
                float4 k4 = *(const float4*)&sh[OFF_KS + d * 64 + jt4];
                s00 += q4.x*k4.x; s01 += q4.x*k4.y; s02 += q4.x*k4.z; s03 += q4.x*k4.w;
                s10 += q4.y*k4.x; s11 += q4.y*k4.y; s12 += q4.y*k4.z; s13 += q4.y*k4.w;
                s20 += q4.z*k4.x; s21 += q4.z*k4.y; s22 += q4.z*k4.z; s23 += q4.z*k4.w;
                s30 += q4.w*k4.x; s31 += q4.w*k4.y; s32 += q4.w*k4.z; s33 += q4.w*k4.w;
            }
            float* srow = &sh[OFF_SS + it4 * SS_LD + jt4];
            srow[0]=s00; srow[1]=s01; srow[2]=s02; srow[3]=s03; srow += SS_LD;
            srow[0]=s10; srow[1]=s11; srow[2]=s12; srow[3]=s13; srow += SS_LD;
            srow[0]=s20; srow[1]=s21; srow[2]=s22; srow[3]=s23; srow += SS_LD;
            srow[0]=s30; srow[1]=s31; srow[2]=s32; srow[3]=s33;
        }
        __syncthreads();

        // Row max + rescale factor (online softmax)
        if (tid < 64) {
            const float* row = &sh[OFF_SS + tid * SS_LD];
            float mx = row[0];
#pragma unroll 8
            for (int j = 1; j < 64; j++) mx = fmaxf(mx, row[j]);
            float mold = sh[OFF_SM + tid];
            float mnew = fmaxf(mold, mx);
            sh[OFF_SM + tid]  = mnew;
            sh[OFF_SAL + tid] = __expf(mold - mnew);
        }
        __syncthreads();

        // P = exp(S - m), partial row sums
        {
            const int r = tid & 63;
            const int q = tid >> 6;
            float mr = sh[OFF_SM + r];
            float* row = &sh[OFF_SS + r * SS_LD + q * 16];
            float psum = 0.f;
#pragma unroll
            for (int j = 0; j < 16; j++) {
                float e = __expf(row[j] - mr);
                row[j] = e;
                psum += e;
            }
            sh[OFF_RED + q * 64 + r] = psum;
        }
        __syncthreads();

        if (tid < 64) {
            sh[OFF_SL + tid] = sh[OFF_SAL + tid] * sh[OFF_SL + tid]
                + sh[OFF_RED + tid]       + sh[OFF_RED + 64 + tid]
                + sh[OFF_RED + 128 + tid] + sh[OFF_RED + 192 + tid];
        }

        // Rescale accumulators
        {
            float al[8];
#pragma unroll
            for (int m = 0; m < 8; m++) al[m] = sh[OFF_SAL + ig * 8 + m];
#pragma unroll
            for (int m = 0; m < 8; m++)
#pragma unroll
                for (int n = 0; n < 8; n++) acc[m][n] *= al[m];
        }

        // O += P * V^T  (outer-product accumulation)
        {
            const float* Pbase = &sh[OFF_SS + (ig * 8) * SS_LD];
            const float* Vbase = &sh[OFF_VS + cg];
#pragma unroll 2
            for (int j = 0; j < 64; j++) {
                float p[8], v[8];
#pragma unroll
                for (int m = 0; m < 8; m++) p[m] = Pbase[m * SS_LD + j];
#pragma unroll
                for (int n = 0; n < 8; n++) v[n] = Vbase[j * VS_LD + 32 * n];
#pragma unroll
                for (int m = 0; m < 8; m++)
#pragma unroll
                    for (int n = 0; n < 8; n++) acc[m][n] += p[m] * v[n];
            }
        }
    }

    __syncthreads();
    float rl[8];
#pragma unroll
    for (int m = 0; m < 8; m++) rl[m] = 1.f / sh[OFF_SL + ig * 8 + m];
    const float gm = gamma_p[0];
    __syncthreads();   // all rl reads done before staging overwrites stats

    // Stage transposed (stride-65) result: stage[c][ii]
#pragma unroll
    for (int m = 0; m < 8; m++) {
        const int ii = ig * 8 + m;
#pragma unroll
        for (int n = 0; n < 8; n++) {
            const int c = cg + 32 * n;
            sh[c * 65 + ii] = gm * acc[m][n] * rl[m];
        }
    }
    __syncthreads();

    const float* xb2 = x   + (size_t)b * 256 * NPIX + i0;
    float*       ob  = out + (size_t)b * 256 * NPIX + i0;
    for (int idx = tid; idx < 16384; idx += 256) {
        int c = idx >> 6, ii = idx & 63;
        ob[c * NPIX + ii] = sh[c * 65 + ii] + xb2[c * NPIX + ii];
    }
}

// ---------------------------------------------------------------------------
extern "C" void kernel_launch(void* const* d_in, const int* in_sizes, int n_in,
                              void* d_out, int out_size)
{
    const float* x     = (const float*)d_in[0];
    const float* wq    = (const float*)d_in[1];
    const float* bq    = (const float*)d_in[2];
    const float* wk    = (const float*)d_in[3];
    const float* bk    = (const float*)d_in[4];
    const float* wv    = (const float*)d_in[5];
    const float* bv    = (const float*)d_in[6];
    const float* gamma = (const float*)d_in[7];
    float* out = (float*)d_out;

    float *qp, *kp, *vp;
    cudaGetSymbolAddress((void**)&qp, g_q);
    cudaGetSymbolAddress((void**)&kp, g_k);
    cudaGetSymbolAddress((void**)&vp, g_v);

    cudaFuncSetAttribute(attn_kernel,
                         cudaFuncAttributeMaxDynamicSharedMemorySize,
                         SMEM_FLOATS * (int)sizeof(float));

    conv3x3_kernel<<<dim3(14, 1, 8), 256>>>(x, wq, bq, qp, 32);
    conv3x3_kernel<<<dim3(14, 1, 8), 256>>>(x, wk, bk, kp, 32);
    conv3x3_kernel<<<dim3(14, 8, 8), 256>>>(x, wv, bv, vp, 256);
    attn_kernel<<<dim3(49, 8), 256, SMEM_FLOATS * sizeof(float)>>>(x, gamma, out);
}

// round 14
// speedup vs baseline: 1.0051x; 1.0051x over previous
#include <cuda_runtime.h>

#define CIN   256
#define HH    56
#define WW    56
#define NPIX  3136
#define BATCH 8

// Scratch (static device globals — allocation-free)
__device__ float g_q[BATCH * 32 * NPIX];
__device__ float g_k[BATCH * 32 * NPIX];
__device__ float g_v[BATCH * 256 * NPIX];

// ---------------------------------------------------------------------------
// 3x3 SAME conv, NCHW / OIHW. Block: 32 out-channels x (4 rows x 56 cols).
// Thread micro-tile: 4 co x 7 px. Cin chunked by 16 through shared memory.
// ---------------------------------------------------------------------------
__global__ __launch_bounds__(256) void conv3x3_kernel(
    const float* __restrict__ x, const float* __restrict__ w,
    const float* __restrict__ bias, float* __restrict__ y, int Cout)
{
    __shared__ float sx[16 * 6 * 58];   // [ci][row(6)][col(58)], halo + zero pad
    __shared__ float sw[144 * 33];      // [(ci*9+tap)][co], stride 33 (conflict-free)

    const int tid  = threadIdx.x;
    const int h0   = blockIdx.x * 4;
    const int co0  = blockIdx.y * 32;
    const int b    = blockIdx.z;

    const int cog  = tid & 7;          // 8 co-groups
    const int pxg  = tid >> 3;         // 32 px-groups
    const int prow = pxg >> 3;         // 0..3
    const int pcol = (pxg & 7) * 7;    // 0,7,...,49
    const int cob  = cog * 4;          // co base within tile

    float acc[4][7];
#pragma unroll
    for (int m = 0; m < 4; m++)
#pragma unroll
        for (int j = 0; j < 7; j++) acc[m][j] = 0.f;

    const float* xb = x + (size_t)b * CIN * NPIX;

    for (int ci0 = 0; ci0 < CIN; ci0 += 16) {
        __syncthreads();
        // Load x chunk with halo (rows h0-1..h0+4, cols -1..56), zero-padded.
        for (int idx = tid; idx < 16 * 6 * 58; idx += 256) {
            int ci  = idx / 348;
            int rem = idx - ci * 348;
            int r   = rem / 58;
            int cc  = rem - r * 58;
            int row = h0 - 1 + r;
            int col = cc - 1;
            float v = 0.f;
            if ((unsigned)row < 56u && (unsigned)col < 56u)
                v = xb[(ci0 + ci) * NPIX + row * WW + col];
            sx[idx] = v;
        }
        // Load weights: global-coalesced in (ci*9+tap); smem stride 33.
        const float* wbase = w + (size_t)co0 * (CIN * 9) + ci0 * 9;
        for (int idx = tid; idx < 32 * 144; idx += 256) {
            int co = idx / 144;
            int ct = idx - co * 144;
            sw[ct * 33 + co] = wbase[(size_t)co * (CIN * 9) + ct];
        }
        __syncthreads();

#pragma unroll 1
        for (int ci = 0; ci < 16; ci++) {
#pragma unroll 1
            for (int kh = 0; kh < 3; kh++) {
                float xv[9];
                const float* sxp = sx + ci * 348 + (prow + kh) * 58 + pcol;
#pragma unroll
                for (int j = 0; j < 9; j++) xv[j] = sxp[j];
                const float* swp = sw + (ci * 9 + kh * 3) * 33 + cob;
#pragma unroll
                for (int kw = 0; kw < 3; kw++) {
                    float w0 = swp[kw * 33 + 0];
                    float w1 = swp[kw * 33 + 1];
                    float w2 = swp[kw * 33 + 2];
                    float w3 = swp[kw * 33 + 3];
#pragma unroll
                    for (int j = 0; j < 7; j++) {
                        float xvj = xv[j + kw];
                        acc[0][j] += w0 * xvj;
                        acc[1][j] += w1 * xvj;
                        acc[2][j] += w2 * xvj;
                        acc[3][j] += w3 * xvj;
                    }
                }
            }
        }
    }

#pragma unroll
    for (int m = 0; m < 4; m++) {
        float bv = bias[co0 + cob + m];
        float* yp = y + ((size_t)(b * Cout + co0 + cob + m)) * NPIX
                      + (h0 + prow) * WW + pcol;
#pragma unroll
        for (int j = 0; j < 7; j++) yp[j] = acc[m][j] + bv;
    }
}

// ---------------------------------------------------------------------------
// Fused flash-attention: per (b, 64-query tile); loops 49 key tiles of 64.
// O accum: 8i x 8c per thread, c interleaved (cg + 32n) for conflict-free V.
// ---------------------------------------------------------------------------
#define OFF_QS   0
#define OFF_KS   2048
#define OFF_SS   4096
#define SS_LD    65
#define OFF_SM   8256
#define OFF_SL   8320
#define OFF_SAL  8384
#define OFF_RED  8448
#define OFF_VS   8704
#define VS_LD    257
#define SMEM_FLOATS 25152   /* 100608 bytes */

__global__ __launch_bounds__(256, 2) void attn_kernel(
    const float* __restrict__ x, const float* __restrict__ gamma_p,
    float* __restrict__ out)
{
    extern __shared__ float sh[];
    const int tid = threadIdx.x;
    const int i0  = blockIdx.x * 64;
    const int b   = blockIdx.y;
    const int ig  = tid >> 5;   // 0..7 : query sub-block
    const int cg  = tid & 31;   // channel lane

    const float* qb = g_q + (size_t)b * 32 * NPIX;
    const float* kb = g_k + (size_t)b * 32 * NPIX;
    const float* vb = g_v + (size_t)b * 256 * NPIX;

    // Q tile: Qs[d][ii]
    for (int idx = tid; idx < 2048; idx += 256) {
        int d = idx >> 6, ii = idx & 63;
        sh[OFF_QS + idx] = qb[d * NPIX + i0 + ii];
    }
    if (tid < 64) {
        sh[OFF_SM + tid] = -1e30f;
        sh[OFF_SL + tid] = 0.f;
    }

    float acc[8][8];
#pragma unroll
    for (int m = 0; m < 8; m++)
#pragma unroll
        for (int n = 0; n < 8; n++) acc[m][n] = 0.f;

    for (int jt = 0; jt < 49; jt++) {
        const int j0 = jt * 64;
        __syncthreads();   // prior PV reads of Ks/Vs/Ss complete
        for (int idx = tid; idx < 2048; idx += 256) {
            int d = idx >> 6, jj = idx & 63;
            sh[OFF_KS + idx] = kb[d * NPIX + j0 + jj];
        }
        for (int idx = tid; idx < 16384; idx += 256) {
            int c = idx >> 6, jj = idx & 63;
            sh[OFF_VS + jj * VS_LD + c] = vb[c * NPIX + j0 + jj];
        }
        __syncthreads();

        // S[ii][jj] = sum_d Q[d][ii] K[d][jj]  (4x4 micro per thread)
        {
            const int jt4 = (tid & 15) * 4;
            const int it4 = (tid >> 4) * 4;
            float s00=0,s01=0,s02=0,s03=0, s10=0,s11=0,s12=0,s13=0;
            float s20=0,s21=0,s22=0,s23=0, s30=0,s31=0,s32=0,s33=0;
#pragma unroll 8
            for (int d = 0; d < 32; d++) {
                float4 q4 = *(const float4*)&sh[OFF_QS + d * 64 + it4];
                float4 k4 = *(const float4*)&sh[OFF_KS + d * 64 + jt4];
                s00 += q4.x*k4.x; s01 += q4.x*k4.y; s02 += q4.x*k4.z; s03 += q4.x*k4.w;
                s10 += q4.y*k4.x; s11 += q4.y*k4.y; s12 += q4.y*k4.z; s13 += q4.y*k4.w;
                s20 += q4.z*k4.x; s21 += q4.z*k4.y; s22 += q4.z*k4.z; s23 += q4.z*k4.w;
                s30 += q4.w*k4.x; s31 += q4.w*k4.y; s32 += q4.w*k4.z; s33 += q4.w*k4.w;
            }
            float* srow = &sh[OFF_SS + it4 * SS_LD + jt4];
            srow[0]=s00; srow[1]=s01; srow[2]=s02; srow[3]=s03; srow += SS_LD;
            srow[0]=s10; srow[1]=s11; srow[2]=s12; srow[3]=s13; srow += SS_LD;
            srow[0]=s20; srow[1]=s21; srow[2]=s22; srow[3]=s23; srow += SS_LD;
            srow[0]=s30; srow[1]=s31; srow[2]=s32; srow[3]=s33;
        }
        __syncthreads();

        // Row max + rescale factor (online softmax)
        if (tid < 64) {
            const float* row = &sh[OFF_SS + tid * SS_LD];
            float mx = row[0];
#pragma unroll 8
            for (int j = 1; j < 64; j++) mx = fmaxf(mx, row[j]);
            float mold = sh[OFF_SM + tid];
            float mnew = fmaxf(mold, mx);
            sh[OFF_SM + tid]  = mnew;
            sh[OFF_SAL + tid] = __expf(mold - mnew);
        }
        __syncthreads();

        // P = exp(S - m), partial row sums
        {
            const int r = tid & 63;
            const int q = tid >> 6;
            float mr = sh[OFF_SM + r];
            float* row = &sh[OFF_SS + r * SS_LD + q * 16];
            float psum = 0.f;
#pragma unroll
            for (int j = 0; j < 16; j++) {
                float e = __expf(row[j] - mr);
                row[j] = e;
                psum += e;
            }
            sh[OFF_RED + q * 64 + r] = psum;
        }
        __syncthreads();

        if (tid < 64) {
            sh[OFF_SL + tid] = sh[OFF_SAL + tid] * sh[OFF_SL + tid]
                + sh[OFF_RED + tid]       + sh[OFF_RED + 64 + tid]
                + sh[OFF_RED + 128 + tid] + sh[OFF_RED + 192 + tid];
        }

        // Rescale accumulators
        {
            float al[8];
#pragma unroll
            for (int m = 0; m < 8; m++) al[m] = sh[OFF_SAL + ig * 8 + m];
#pragma unroll
            for (int m = 0; m < 8; m++)
#pragma unroll
                for (int n = 0; n < 8; n++) acc[m][n] *= al[m];
        }

        // O += P * V^T  (outer-product accumulation)
        {
            const float* Pbase = &sh[OFF_SS + (ig * 8) * SS_LD];
            const float* Vbase = &sh[OFF_VS + cg];
#pragma unroll 2
            for (int j = 0; j < 64; j++) {
                float p[8], v[8];
#pragma unroll
                for (int m = 0; m < 8; m++) p[m] = Pbase[m * SS_LD + j];
#pragma unroll
                for (int n = 0; n < 8; n++) v[n] = Vbase[j * VS_LD + 32 * n];
#pragma unroll
                for (int m = 0; m < 8; m++)
#pragma unroll
                    for (int n = 0; n < 8; n++) acc[m][n] += p[m] * v[n];
            }
        }
    }

    __syncthreads();
    float rl[8];
#pragma unroll
    for (int m = 0; m < 8; m++) rl[m] = 1.f / sh[OFF_SL + ig * 8 + m];
    const float gm = gamma_p[0];
    __syncthreads();   // all rl reads done before staging overwrites stats

    // Stage transposed (stride-65) result: stage[c][ii]
#pragma unroll
    for (int m = 0; m < 8; m++) {
        const int ii = ig * 8 + m;
#pragma unroll
        for (int n = 0; n < 8; n++) {
            const int c = cg + 32 * n;
            sh[c * 65 + ii] = gm * acc[m][n] * rl[m];
        }
    }
    __syncthreads();

    const float* xb2 = x   + (size_t)b * 256 * NPIX + i0;
    float*       ob  = out + (size_t)b * 256 * NPIX + i0;
    for (int idx = tid; idx < 16384; idx += 256) {
        int c = idx >> 6, ii = idx & 63;
        ob[c * NPIX + ii] = sh[c * 65 + ii] + xb2[c * NPIX + ii];
    }
}

// ---------------------------------------------------------------------------
extern "C" void kernel_launch(void* const* d_in, const int* in_sizes, int n_in,
                              void* d_out, int out_size)
{
    const float* x     = (const float*)d_in[0];
    const float* wq    = (const float*)d_in[1];
    const float* bq    = (const float*)d_in[2];
    const float* wk    = (const float*)d_in[3];
    const float* bk    = (const float*)d_in[4];
    const float* wv    = (const float*)d_in[5];
    const float* bv    = (const float*)d_in[6];
    const float* gamma = (const float*)d_in[7];
    float* out = (float*)d_out;

    float *qp, *kp, *vp;
    cudaGetSymbolAddress((void**)&qp, g_q);
    cudaGetSymbolAddress((void**)&kp, g_k);
    cudaGetSymbolAddress((void**)&vp, g_v);

    cudaFuncSetAttribute(attn_kernel,
                         cudaFuncAttributeMaxDynamicSharedMemorySize,
                         SMEM_FLOATS * (int)sizeof(float));

    conv3x3_kernel<<<dim3(14, 1, 8), 256>>>(x, wq, bq, qp, 32);
    conv3x3_kernel<<<dim3(14, 1, 8), 256>>>(x, wk, bk, kp, 32);
    conv3x3_kernel<<<dim3(14, 8, 8), 256>>>(x, wv, bv, vp, 256);
    attn_kernel<<<dim3(49, 8), 256, SMEM_FLOATS * sizeof(float)>>>(x, gamma, out);
}

// round 15
// speedup vs baseline: 1.0082x; 1.0030x over previous
#include <cuda_runtime.h>

#define CIN   256
#define HH    56
#define WW    56
#define NPIX  3136
#define BATCH 8

// Scratch (static device globals — allocation-free)
__device__ float g_q[BATCH * 32 * NPIX];
__device__ float g_k[BATCH * 32 * NPIX];
__device__ float g_v[BATCH * 256 * NPIX];

// ---------------------------------------------------------------------------
// 3x3 SAME conv, NCHW / OIHW. Block: 32 out-channels x (4 rows x 56 cols).
// Thread micro-tile: 4 co x 7 px. Cin chunked by 16 through shared memory.
// ---------------------------------------------------------------------------
__global__ __launch_bounds__(256) void conv3x3_kernel(
    const float* __restrict__ x, const float* __restrict__ w,
    const float* __restrict__ bias, float* __restrict__ y, int Cout)
{
    __shared__ float sx[16 * 6 * 58];   // [ci][row(6)][col(58)], halo + zero pad
    __shared__ float sw[144 * 33];      // [(ci*9+tap)][co], stride 33 (conflict-free)

    const int tid  = threadIdx.x;
    const int h0   = blockIdx.x * 4;
    const int co0  = blockIdx.y * 32;
    const int b    = blockIdx.z;

    const int cog  = tid & 7;          // 8 co-groups
    const int pxg  = tid >> 3;         // 32 px-groups
    const int prow = pxg >> 3;         // 0..3
    const int pcol = (pxg & 7) * 7;    // 0,7,...,49
    const int cob  = cog * 4;          // co base within tile

    float acc[4][7];
#pragma unroll
    for (int m = 0; m < 4; m++)
#pragma unroll
        for (int j = 0; j < 7; j++) acc[m][j] = 0.f;

    const float* xb = x + (size_t)b * CIN * NPIX;

    for (int ci0 = 0; ci0 < CIN; ci0 += 16) {
        __syncthreads();
        // Load x chunk with halo (rows h0-1..h0+4, cols -1..56), zero-padded.
        for (int idx = tid; idx < 16 * 6 * 58; idx += 256) {
            int ci  = idx / 348;
            int rem = idx - ci * 348;
            int r   = rem / 58;
            int cc  = rem - r * 58;
            int row = h0 - 1 + r;
            int col = cc - 1;
            float v = 0.f;
            if ((unsigned)row < 56u && (unsigned)col < 56u)
                v = xb[(ci0 + ci) * NPIX + row * WW + col];
            sx[idx] = v;
        }
        // Load weights: global-coalesced in (ci*9+tap); smem stride 33.
        const float* wbase = w + (size_t)co0 * (CIN * 9) + ci0 * 9;
        for (int idx = tid; idx < 32 * 144; idx += 256) {
            int co = idx / 144;
            int ct = idx - co * 144;
            sw[ct * 33 + co] = wbase[(size_t)co * (CIN * 9) + ct];
        }
        __syncthreads();

#pragma unroll 1
        for (int ci = 0; ci < 16; ci++) {
#pragma unroll 1
            for (int kh = 0; kh < 3; kh++) {
                float xv[9];
                const float* sxp = sx + ci * 348 + (prow + kh) * 58 + pcol;
#pragma unroll
                for (int j = 0; j < 9; j++) xv[j] = sxp[j];
                const float* swp = sw + (ci * 9 + kh * 3) * 33 + cob;
#pragma unroll
                for (int kw = 0; kw < 3; kw++) {
                    float w0 = swp[kw * 33 + 0];
                    float w1 = swp[kw * 33 + 1];
                    float w2 = swp[kw * 33 + 2];
                    float w3 = swp[kw * 33 + 3];
#pragma unroll
                    for (int j = 0; j < 7; j++) {
                        float xvj = xv[j + kw];
                        acc[0][j] += w0 * xvj;
                        acc[1][j] += w1 * xvj;
                        acc[2][j] += w2 * xvj;
                        acc[3][j] += w3 * xvj;
                    }
                }
            }
        }
    }

#pragma unroll
    for (int m = 0; m < 4; m++) {
        float bv = bias[co0 + cob + m];
        float* yp = y + ((size_t)(b * Cout + co0 + cob + m)) * NPIX
                      + (h0 + prow) * WW + pcol;
#pragma unroll
        for (int j = 0; j < 7; j++) yp[j] = acc[m][j] + bv;
    }
}

// ---------------------------------------------------------------------------
// Fused flash-attention: per (b, 64-query tile); loops 49 key tiles of 64.
// O accum: 8i x 8c per thread, c interleaved (cg + 32n) for conflict-free V.
// ---------------------------------------------------------------------------
#define OFF_QS   0
#define OFF_KS   2048
#define OFF_SS   4096
#define SS_LD    65
#define OFF_SM   8256
#define OFF_SL   8320
#define OFF_SAL  8384
#define OFF_RED  8448
#define OFF_VS   8704
#define VS_LD    257
#define SMEM_FLOATS 25152   /* 100608 bytes */

__global__ __launch_bounds__(256, 2) void attn_kernel(
    const float* __restrict__ x, const float* __restrict__ gamma_p,
    float* __restrict__ out)
{
    extern __shared__ float sh[];
    const int tid = threadIdx.x;
    const int i0  = blockIdx.x * 64;
    const int b   = blockIdx.y;
    const int ig  = tid >> 5;   // 0..7 : query sub-block
    const int cg  = tid & 31;   // channel lane

    const float* qb = g_q + (size_t)b * 32 * NPIX;
    const float* kb = g_k + (size_t)b * 32 * NPIX;
    const float* vb = g_v + (size_t)b * 256 * NPIX;

    // Q tile: Qs[d][ii]
    for (int idx = tid; idx < 2048; idx += 256) {
        int d = idx >> 6, ii = idx & 63;
        sh[OFF_QS + idx] = qb[d * NPIX + i0 + ii];
    }
    if (tid < 64) {
        sh[OFF_SM + tid] = -1e30f;
        sh[OFF_SL + tid] = 0.f;
    }

    float acc[8][8];
#pragma unroll
    for (int m = 0; m < 8; m++)
#pragma unroll
        for (int n = 0; n < 8; n++) acc[m][n] = 0.f;

    for (int jt = 0; jt < 49; jt++) {
        const int j0 = jt * 64;
        __syncthreads();   // prior PV reads of Ks/Vs/Ss complete
        for (int idx = tid; idx < 2048; idx += 256) {
            int d = idx >> 6, jj = idx & 63;
            sh[OFF_KS + idx] = kb[d * NPIX + j0 + jj];
        }
        for (int idx = tid; idx < 16384; idx += 256) {
            int c = idx >> 6, jj = idx & 63;
            sh[OFF_VS + jj * VS_LD + c] = vb[c * NPIX + j0 + jj];
        }
        __syncthreads();

        // S[ii][jj] = sum_d Q[d][ii] K[d][jj]  (4x4 micro per thread)
        {
            const int jt4 = (tid & 15) * 4;
            const int it4 = (tid >> 4) * 4;
            float s00=0,s01=0,s02=0,s03=0, s10=0,s11=0,s12=0,s13=0;
            float s20=0,s21=0,s22=0,s23=0, s30=0,s31=0,s32=0,s33=0;
#pragma unroll 8
            for (int d = 0; d < 32; d++) {
                float4 q4 = *(const float4*)&sh[OFF_QS + d * 64 + it4];
                float4 k4 = *(const float4*)&sh[OFF_KS + d * 64 + jt4];
                s00 += q4.x*k4.x; s01 += q4.x*k4.y; s02 += q4.x*k4.z; s03 += q4.x*k4.w;
                s10 += q4.y*k4.x; s11 += q4.y*k4.y; s12 += q4.y*k4.z; s13 += q4.y*k4.w;
                s20 += q4.z*k4.x; s21 += q4.z*k4.y; s22 += q4.z*k4.z; s23 += q4.z*k4.w;
                s30 += q4.w*k4.x; s31 += q4.w*k4.y; s32 += q4.w*k4.z; s33 += q4.w*k4.w;
            }
            float* srow = &sh[OFF_SS + it4 * SS_LD + jt4];
            srow[0]=s00; srow[1]=s01; srow[2]=s02; srow[3]=s03; srow += SS_LD;
            srow[0]=s10; srow[1]=s11; srow[2]=s12; srow[3]=s13; srow += SS_LD;
            srow[0]=s20; srow[1]=s21; srow[2]=s22; srow[3]=s23; srow += SS_LD;
            srow[0]=s30; srow[1]=s31; srow[2]=s32; srow[3]=s33;
        }
        __syncthreads();

        // Row max + rescale factor (online softmax)
        if (tid < 64) {
            const float* row = &sh[OFF_SS + tid * SS_LD];
            float mx = row[0];
#pragma unroll 8
            for (int j = 1; j < 64; j++) mx = fmaxf(mx, row[j]);
            float mold = sh[OFF_SM + tid];
            float mnew = fmaxf(mold, mx);
            sh[OFF_SM + tid]  = mnew;
            sh[OFF_SAL + tid] = __expf(mold - mnew);
        }
        __syncthreads();

        // P = exp(S - m), partial row sums
        {
            const int r = tid & 63;
            const int q = tid >> 6;
            float mr = sh[OFF_SM + r];
            float* row = &sh[OFF_SS + r * SS_LD + q * 16];
            float psum = 0.f;
#pragma unroll
            for (int j = 0; j < 16; j++) {
                float e = __expf(row[j] - mr);
                row[j] = e;
                psum += e;
            }
            sh[OFF_RED + q * 64 + r] = psum;
        }
        __syncthreads();

        if (tid < 64) {
            sh[OFF_SL + tid] = sh[OFF_SAL + tid] * sh[OFF_SL + tid]
                + sh[OFF_RED + tid]       + sh[OFF_RED + 64 + tid]
                + sh[OFF_RED + 128 + tid] + sh[OFF_RED + 192 + tid];
        }

        // Rescale accumulators
        {
            float al[8];
#pragma unroll
            for (int m = 0; m < 8; m++) al[m] = sh[OFF_SAL + ig * 8 + m];
#pragma unroll
            for (int m = 0; m < 8; m++)
#pragma unroll
                for (int n = 0; n < 8; n++) acc[m][n] *= al[m];
        }

        // O += P * V^T  (outer-product accumulation)
        {
            const float* Pbase = &sh[OFF_SS + (ig * 8) * SS_LD];
            const float* Vbase = &sh[OFF_VS + cg];
#pragma unroll 2
            for (int j = 0; j < 64; j++) {
                float p[8], v[8];
#pragma unroll
                for (int m = 0; m < 8; m++) p[m] = Pbase[m * SS_LD + j];
#pragma unroll
                for (int n = 0; n < 8; n++) v[n] = Vbase[j * VS_LD + 32 * n];
#pragma unroll
                for (int m = 0; m < 8; m++)
#pragma unroll
                    for (int n = 0; n < 8; n++) acc[m][n] += p[m] * v[n];
            }
        }
    }

    __syncthreads();
    float rl[8];
#pragma unroll
    for (int m = 0; m < 8; m++) rl[m] = 1.f / sh[OFF_SL + ig * 8 + m];
    const float gm = gamma_p[0];
    __syncthreads();   // all rl reads done before staging overwrites stats

    // Stage transposed (stride-65) result: stage[c][ii]
#pragma unroll
    for (int m = 0; m < 8; m++) {
        const int ii = ig * 8 + m;
#pragma unroll
        for (int n = 0; n < 8; n++) {
            const int c = cg + 32 * n;
            sh[c * 65 + ii] = gm * acc[m][n] * rl[m];
        }
    }
    __syncthreads();

    const float* xb2 = x   + (size_t)b * 256 * NPIX + i0;
    float*       ob  = out + (size_t)b * 256 * NPIX + i0;
    for (int idx = tid; idx < 16384; idx += 256) {
        int c = idx >> 6, ii = idx & 63;
        ob[c * NPIX + ii] = sh[c * 65 + ii] + xb2[c * NPIX + ii];
    }
}

// ---------------------------------------------------------------------------
extern "C" void kernel_launch(void* const* d_in, const int* in_sizes, int n_in,
                              void* d_out, int out_size)
{
    const float* x     = (const float*)d_in[0];
    const float* wq    = (const float*)d_in[1];
    const float* bq    = (const float*)d_in[2];
    const float* wk    = (const float*)d_in[3];
    const float* bk    = (const float*)d_in[4];
    const float* wv    = (const float*)d_in[5];
    const float* bv    = (const float*)d_in[6];
    const float* gamma = (const float*)d_in[7];
    float* out = (float*)d_out;

    float *qp, *kp, *vp;
    cudaGetSymbolAddress((void**)&qp, g_q);
    cudaGetSymbolAddress((void**)&kp, g_k);
    cudaGetSymbolAddress((void**)&vp, g_v);

    cudaFuncSetAttribute(attn_kernel,
                         cudaFuncAttributeMaxDynamicSharedMemorySize,
                         SMEM_FLOATS * (int)sizeof(float));

    conv3x3_kernel<<<dim3(14, 1, 8), 256>>>(x, wq, bq, qp, 32);
    conv3x3_kernel<<<dim3(14, 1, 8), 256>>>(x, wk, bk, kp, 32);
    conv3x3_kernel<<<dim3(14, 8, 8), 256>>>(x, wv, bv, vp, 256);
    attn_kernel<<<dim3(49, 8), 256, SMEM_FLOATS * sizeof(float)>>>(x, gamma, out);
}